// round 11
// baseline (speedup 1.0000x reference)
#include <cuda_runtime.h>

// Problem constants
#define NB   2
#define C    128
#define H    64
#define WID  64
#define HW   4096       // H*W
#define KK   81         // L*L
#define PADR 4          // L/2

// sim kernel tiling (2x16 px tiles -> 256 blocks, 288 threads)
#define BTH  2
#define BTW  16
#define BTP  32         // px per tile
#define BHY  10         // 2 + 8 halo rows
#define BHX  24
#define BKST 28         // padded halo row stride
#define CCB  32         // channel chunk
#define SIMN 2592       // BTP*KK

// weighting kernel tiling (4x16 px tiles x 4 channel chunks -> 512 blocks)
#define TH   4
#define TW   16
#define TP   64
#define HY   12
#define HX   24
#define KST  28
#define CCD  32
#define WST  68

#define GK   16         // gemm W k-chunk

// Scratch (allocation-free rule: __device__ globals)
__device__ float g_key   [NB * C * HW];
__device__ float g_query [NB * C * HW];
__device__ float g_weight[NB * HW * KK];

// ---- packed fp32x2 helpers (sm_100+: ptxas never emits FFMA2 from C++) ----
typedef unsigned long long u64;
__device__ __forceinline__ u64 pk(float lo, float hi) {
    u64 r; asm("mov.b64 %0, {%1, %2};" : "=l"(r) : "f"(lo), "f"(hi)); return r;
}
__device__ __forceinline__ void fma2(u64& d, u64 a, u64 b) {
    asm("fma.rn.f32x2 %0, %1, %2, %0;" : "+l"(d) : "l"(a), "l"(b));
}
__device__ __forceinline__ float2 upk(u64 v) {
    float2 r; asm("mov.b64 {%0, %1}, %2;" : "=f"(r.x), "=f"(r.y) : "l"(v)); return r;
}

// ---------------------------------------------------------------------------
// Kernel A: 1x1-conv projections (R8 version — proven 20.3us).
// grid = (64, 4). Full X tile resident; W double-buffered 16-k chunks.
// ---------------------------------------------------------------------------
__global__ __launch_bounds__(256) void gemm_kernel(
        const float* __restrict__ ft, const float* __restrict__ fk,
        const float* __restrict__ Wm)
{
    extern __shared__ float sm[];
    float* Xs = sm;                 // [128][64]
    float* Ws = sm + 128 * 64;      // [2][GK][128]

    const int t  = threadIdx.x;
    const int p0 = blockIdx.x * 64;
    const int n  = blockIdx.y & 1;
    const int which = blockIdx.y >> 1;
    const float* X = (which ? fk : ft) + n * C * HW;
    float*       Y = (which ? g_query : g_key) + n * C * HW;

    const int px  = (t & 15) * 4;
    const int co8 = (t >> 4) * 8;

    {
        const int cc = t >> 4;
        const int xp = (t & 15) * 4;
        #pragma unroll
        for (int it = 0; it < 8; it++) {
            int c = cc + it * 16;
            *(float4*)&Xs[c * 64 + xp] = *(const float4*)&X[c * HW + p0 + xp];
        }
    }
    const int so  = t >> 1;
    const int sk4 = (t & 1) * 8;
    auto stageW = [&](int buf, int kb) {
        float* Wb = Ws + buf * (GK * 128);
        #pragma unroll
        for (int j = 0; j < 2; j++) {
            int k4 = sk4 + j * 4;
            float4 wv = *(const float4*)&Wm[so * C + kb + k4];
            Wb[(k4 + 0) * 128 + so] = wv.x;
            Wb[(k4 + 1) * 128 + so] = wv.y;
            Wb[(k4 + 2) * 128 + so] = wv.z;
            Wb[(k4 + 3) * 128 + so] = wv.w;
        }
    };
    stageW(0, 0);

    u64 acc[4][4] = {};
    __syncthreads();

    int buf = 0;
    for (int kb = 0; kb < 8; kb++) {
        if (kb < 7) stageW(buf ^ 1, (kb + 1) * GK);
        const float* Wb = Ws + buf * (GK * 128);
        const float* Xb = Xs + (kb * GK) * 64;
        #pragma unroll
        for (int kk = 0; kk < GK; kk++) {
            float4 a0 = *(const float4*)&Wb[kk * 128 + co8];
            float4 a1 = *(const float4*)&Wb[kk * 128 + co8 + 4];
            float4 b  = *(const float4*)&Xb[kk * 64 + px];
            u64 ap0 = pk(a0.x, a0.y), ap1 = pk(a0.z, a0.w);
            u64 ap2 = pk(a1.x, a1.y), ap3 = pk(a1.z, a1.w);
            u64 b0 = pk(b.x, b.x), b1 = pk(b.y, b.y);
            u64 b2 = pk(b.z, b.z), b3 = pk(b.w, b.w);
            fma2(acc[0][0], ap0, b0); fma2(acc[0][1], ap0, b1);
            fma2(acc[0][2], ap0, b2); fma2(acc[0][3], ap0, b3);
            fma2(acc[1][0], ap1, b0); fma2(acc[1][1], ap1, b1);
            fma2(acc[1][2], ap1, b2); fma2(acc[1][3], ap1, b3);
            fma2(acc[2][0], ap2, b0); fma2(acc[2][1], ap2, b1);
            fma2(acc[2][2], ap2, b2); fma2(acc[2][3], ap2, b3);
            fma2(acc[3][0], ap3, b0); fma2(acc[3][1], ap3, b1);
            fma2(acc[3][2], ap3, b2); fma2(acc[3][3], ap3, b3);
        }
        __syncthreads();
        buf ^= 1;
    }

    #pragma unroll
    for (int j2 = 0; j2 < 4; j2++) {
        float2 v0 = upk(acc[j2][0]), v1 = upk(acc[j2][1]);
        float2 v2 = upk(acc[j2][2]), v3 = upk(acc[j2][3]);
        *(float4*)&Y[(co8 + 2 * j2)     * HW + p0 + px] =
            make_float4(v0.x, v1.x, v2.x, v3.x);
        *(float4*)&Y[(co8 + 2 * j2 + 1) * HW + p0 + px] =
            make_float4(v0.y, v1.y, v2.y, v3.y);
    }
}

// ---------------------------------------------------------------------------
// Kernel B: sim + softmax. 256 blocks (2x16 px tiles), 288 threads:
//   t -> (cq = t/72 (4-way channel split), di = (t%72)/8, px-group = t%8)
// Staging uses FIXED per-thread (hy,hx)/(px) coordinates — no div/mod in
// loops. Partials merged into 2 smem arrays; final sum folded into softmax.
// ---------------------------------------------------------------------------
__global__ __launch_bounds__(288) void sim_softmax_kernel()
{
    extern __shared__ float sm[];
    float* ks   = sm;                      // CCB*BHY*BKST = 8960 floats
    float* qs   = ks + CCB * BHY * BKST;   // CCB*BTP      = 1024
    float* simp = qs + CCB * BTP;          // 2*SIMN       = 5184

    const int t   = threadIdx.x;
    const int bx  = blockIdx.x;
    const int n   = bx >> 7;
    const int rem = bx & 127;
    const int ty0 = (rem >> 2) * BTH;
    const int tx0 = (rem & 3) * BTW;

    const float* keyg = g_key   + n * C * HW;
    const float* qg   = g_query + n * C * HW;

    // fixed staging coordinates (computed once)
    const int shy = t / 24;                // halo row   (valid if t < 240)
    const int shx = t - shy * 24;          // halo col
    const int sgy = ty0 + shy - PADR;
    const int sgx = tx0 + shx - PADR;
    const bool sval = (t < 240) && ((unsigned)sgy < H) && ((unsigned)sgx < WID);
    const int sgo = sgy * WID + sgx;       // gmem offset (garbage if !sval)
    const int sso = shy * BKST + shx;      // smem offset
    const int qpx = t & 31;                // q px (valid if t < 256)
    const int qc0 = (t >> 5) & 7;          // q start channel
    const int qpy = (ty0 + (qpx >> 4)) * WID + tx0 + (qpx & 15);

    const int cq  = t / 72;
    const int r   = t - cq * 72;
    const int di  = r >> 3;
    const int pxg = r & 7;
    const int ly  = pxg >> 2;
    const int lxg = (pxg & 3) * 4;

    u64 accp[9][2] = {};

    for (int cc = 0; cc < C; cc += CCB) {
        // key halo: each of 240 threads owns one (hy,hx); loop channels
        if (t < 240) {
            const float* src = keyg + cc * HW + sgo;
            float* dst = ks + sso;
            #pragma unroll 8
            for (int c = 0; c < CCB; c++) {
                dst[c * (BHY * BKST)] = sval ? src[c * HW] : 0.f;
            }
        }
        // query tile: each of 256 threads owns one px; 4 channels each
        if (t < 256) {
            const float* src = qg + cc * HW + qpy;
            #pragma unroll
            for (int c = qc0; c < CCB; c += 8)
                qs[c * BTP + qpx] = src[c * HW];
        }
        __syncthreads();

        const int cbeg = cq * 8;
        #pragma unroll 2
        for (int c = cbeg; c < cbeg + 8; c++) {
            float4 q4 = *(const float4*)&qs[c * BTP + ly * BTW + lxg];
            const float* kp = &ks[c * (BHY * BKST) + (ly + di) * BKST + lxg];
            float4 k0 = *(const float4*)kp;
            float4 k1 = *(const float4*)(kp + 4);
            float4 k2 = *(const float4*)(kp + 8);
            const float kr[12] = {k0.x, k0.y, k0.z, k0.w,
                                  k1.x, k1.y, k1.z, k1.w,
                                  k2.x, k2.y, k2.z, k2.w};
            u64 q01 = pk(q4.x, q4.y), q23 = pk(q4.z, q4.w);
            u64 win[11];
            #pragma unroll
            for (int m = 0; m < 11; m++) win[m] = pk(kr[m], kr[m + 1]);
            #pragma unroll
            for (int dj = 0; dj < 9; dj++) {
                fma2(accp[dj][0], q01, win[dj]);
                fma2(accp[dj][1], q23, win[dj + 2]);
            }
        }
        __syncthreads();
    }

    // merge 4 partials into 2 arrays (cq0,1 -> sp0; cq2,3 -> sp1)
    const int pxb = ly * BTW + lxg;
    float* sp = simp + (cq >> 1) * SIMN;
    if ((cq & 1) == 0) {
        #pragma unroll
        for (int dj = 0; dj < 9; dj++) {
            float2 v0 = upk(accp[dj][0]), v1 = upk(accp[dj][1]);
            sp[(pxb + 0) * KK + di * 9 + dj] = v0.x;
            sp[(pxb + 1) * KK + di * 9 + dj] = v0.y;
            sp[(pxb + 2) * KK + di * 9 + dj] = v1.x;
            sp[(pxb + 3) * KK + di * 9 + dj] = v1.y;
        }
    }
    __syncthreads();
    if (cq & 1) {
        #pragma unroll
        for (int dj = 0; dj < 9; dj++) {
            float2 v0 = upk(accp[dj][0]), v1 = upk(accp[dj][1]);
            sp[(pxb + 0) * KK + di * 9 + dj] += v0.x;
            sp[(pxb + 1) * KK + di * 9 + dj] += v0.y;
            sp[(pxb + 2) * KK + di * 9 + dj] += v1.x;
            sp[(pxb + 3) * KK + di * 9 + dj] += v1.y;
        }
    }
    __syncthreads();

    // softmax over 81 taps: 8 lanes per pixel; fold sp0+sp1 in the max pass
    if (t < 256) {
        const int px = t >> 3;
        const int q  = t & 7;
        float* r0 = &simp[px * KK];
        float* r1 = r0 + SIMN;
        float m = -1e30f;
        for (int k = q; k < KK; k += 8) {
            float v = r0[k] + r1[k];
            r0[k] = v;
            m = fmaxf(m, v);
        }
        m = fmaxf(m, __shfl_xor_sync(0xffffffffu, m, 1));
        m = fmaxf(m, __shfl_xor_sync(0xffffffffu, m, 2));
        m = fmaxf(m, __shfl_xor_sync(0xffffffffu, m, 4));
        float s = 0.f;
        for (int k = q; k < KK; k += 8) {
            float e = __expf(r0[k] - m);
            r0[k] = e;
            s += e;
        }
        s += __shfl_xor_sync(0xffffffffu, s, 1);
        s += __shfl_xor_sync(0xffffffffu, s, 2);
        s += __shfl_xor_sync(0xffffffffu, s, 4);
        const float inv = 1.f / s;
        float* wout = &g_weight[((n * H + ty0 + (px >> 4)) * WID + tx0 + (px & 15)) * KK];
        for (int k = q; k < KK; k += 8) wout[k] = r0[k] * inv;
    }
}

// ---------------------------------------------------------------------------
// Kernel D: out[c][p] = sum_k weight[p][k] * ft[c][p + off_k]  (zero-padded)
// grid = (128 tiles, 4 channel chunks), 288 threads (12x24 = 288 fixed halo
// coords, exact fit). ws staged with incremental k/px (no div in loop).
// Compute uses first 256 threads (as R8).
// ---------------------------------------------------------------------------
__global__ __launch_bounds__(288) void weight_kernel(
        const float* __restrict__ ft, float* __restrict__ out)
{
    extern __shared__ float sm[];
    float* fts = sm;                    // CCD*HY*KST = 10752 floats
    float* ws  = fts + CCD * HY * KST;  // KK*WST     =  5508

    const int t   = threadIdx.x;
    const int bx  = blockIdx.x;
    const int n   = bx >> 6;
    const int rem = bx & 63;
    const int ty0 = (rem >> 2) * TH;
    const int tx0 = (rem & 3) * TW;
    const int c0  = blockIdx.y * CCD;
    const float* ftn = ft + n * C * HW;

    // ws staging: 5184 elements over 288 threads = 18 iters, incremental idx
    {
        int k  = t % 81;
        int px = t / 81;
        const float* wbase = g_weight + (size_t)n * HW * KK;
        #pragma unroll
        for (int it = 0; it < 18; it++) {
            int py = (ty0 + (px >> 4)) * WID + tx0 + (px & 15);
            ws[k * WST + px] = wbase[py * KK + k];
            px += 3; k += 45;
            if (k >= 81) { k -= 81; px += 1; }
        }
    }
    // ft halo staging: fixed (hy,hx) per thread (12x24 = 288), loop channels
    {
        const int hy = t / 24;
        const int hx = t - hy * 24;
        const int gy = ty0 + hy - PADR;
        const int gx = tx0 + hx - PADR;
        const bool val = ((unsigned)gy < H) && ((unsigned)gx < WID);
        const int go = gy * WID + gx;
        const float* src = ftn + c0 * HW + go;
        float* dst = fts + hy * KST + hx;
        #pragma unroll 8
        for (int c = 0; c < CCD; c++)
            dst[c * (HY * KST)] = val ? src[c * HW] : 0.f;
    }
    __syncthreads();

    if (t < 256) {
        const int pxg = t & 15;
        const int cl  = (t >> 4) * 2;
        const int ly  = pxg >> 2;
        const int lxg = (pxg & 3) * 4;
        u64 ap0[2] = {}, ap1[2] = {};

        #pragma unroll
        for (int di = 0; di < 9; di++) {
            const float* f0 = &fts[cl * (HY * KST) + (ly + di) * KST + lxg];
            const float* f1 = f0 + HY * KST;
            float4 x0 = *(const float4*)f0;
            float4 x1 = *(const float4*)(f0 + 4);
            float4 x2 = *(const float4*)(f0 + 8);
            float4 y0 = *(const float4*)f1;
            float4 y1 = *(const float4*)(f1 + 4);
            float4 y2 = *(const float4*)(f1 + 8);
            const float fr0[12] = {x0.x, x0.y, x0.z, x0.w, x1.x, x1.y, x1.z, x1.w,
                                   x2.x, x2.y, x2.z, x2.w};
            const float fr1[12] = {y0.x, y0.y, y0.z, y0.w, y1.x, y1.y, y1.z, y1.w,
                                   y2.x, y2.y, y2.z, y2.w};
            u64 w0[11], w1[11];
            #pragma unroll
            for (int m = 0; m < 11; m++) {
                w0[m] = pk(fr0[m], fr0[m + 1]);
                w1[m] = pk(fr1[m], fr1[m + 1]);
            }
            #pragma unroll
            for (int dj = 0; dj < 9; dj++) {
                float4 w4 = *(const float4*)&ws[(di * 9 + dj) * WST + ly * TW + lxg];
                u64 w01 = pk(w4.x, w4.y), w23 = pk(w4.z, w4.w);
                fma2(ap0[0], w01, w0[dj]);
                fma2(ap0[1], w23, w0[dj + 2]);
                fma2(ap1[0], w01, w1[dj]);
                fma2(ap1[1], w23, w1[dj + 2]);
            }
        }

        float* on = out + n * C * HW;
        const int pix = (ty0 + ly) * WID + tx0 + lxg;
        {
            float2 v0 = upk(ap0[0]), v1 = upk(ap0[1]);
            *(float4*)&on[(c0 + cl) * HW + pix] = make_float4(v0.x, v0.y, v1.x, v1.y);
        }
        {
            float2 v0 = upk(ap1[0]), v1 = upk(ap1[1]);
            *(float4*)&on[(c0 + cl + 1) * HW + pix] = make_float4(v0.x, v0.y, v1.x, v1.y);
        }
    }
}

// ---------------------------------------------------------------------------
extern "C" void kernel_launch(void* const* d_in, const int* in_sizes, int n_in,
                              void* d_out, int out_size)
{
    const float* ft = (const float*)d_in[0];
    const float* fk = (const float*)d_in[1];
    const float* Wm = (const float*)d_in[2];
    float* out = (float*)d_out;

    const int smA = (128 * 64 + 2 * GK * 128) * (int)sizeof(float);                 // 49152
    const int smB = (CCB * BHY * BKST + CCB * BTP + 2 * SIMN) * (int)sizeof(float); // 60672
    const int smD = (CCD * HY * KST + KK * WST) * (int)sizeof(float);               // 65040
    cudaFuncSetAttribute(gemm_kernel,
                         cudaFuncAttributeMaxDynamicSharedMemorySize, smA);
    cudaFuncSetAttribute(sim_softmax_kernel,
                         cudaFuncAttributeMaxDynamicSharedMemorySize, smB);
    cudaFuncSetAttribute(weight_kernel,
                         cudaFuncAttributeMaxDynamicSharedMemorySize, smD);

    gemm_kernel<<<dim3(HW / 64, 4), 256, smA>>>(ft, fk, Wm);
    sim_softmax_kernel<<<NB * (H / BTH) * (WID / BTW), 288, smB>>>();
    weight_kernel<<<dim3(NB * (H / TH) * (WID / TW), C / CCD), 288, smD>>>(ft, out);
}

// round 14
// speedup vs baseline: 1.4273x; 1.4273x over previous
#include <cuda_runtime.h>

// Problem constants
#define NB   2
#define C    128
#define H    64
#define WID  64
#define HW   4096       // H*W
#define KK   81         // L*L
#define PADR 4          // L/2

// fused kernel tiling (2x16 px tiles -> 256 blocks, 288 threads)
#define BTH  2
#define BTW  16
#define BTP  32         // px per tile
#define BHY  10         // 2 + 8 halo rows
#define BHX  24
#define BKST 28         // padded halo row stride
#define CCB  32         // channel chunk
#define SIMN 2592       // BTP*KK
#define WDS  36         // wd row stride (mult of 4, conflict-free)

#define GK   16         // gemm W k-chunk

// Scratch (allocation-free rule: __device__ globals)
__device__ float g_key   [NB * C * HW];
__device__ float g_query [NB * C * HW];

// ---- packed fp32x2 helpers (sm_100+: ptxas never emits FFMA2 from C++) ----
typedef unsigned long long u64;
__device__ __forceinline__ u64 pk(float lo, float hi) {
    u64 r; asm("mov.b64 %0, {%1, %2};" : "=l"(r) : "f"(lo), "f"(hi)); return r;
}
__device__ __forceinline__ void fma2(u64& d, u64 a, u64 b) {
    asm("fma.rn.f32x2 %0, %1, %2, %0;" : "+l"(d) : "l"(a), "l"(b));
}
__device__ __forceinline__ float2 upk(u64 v) {
    float2 r; asm("mov.b64 {%0, %1}, %2;" : "=f"(r.x), "=f"(r.y) : "l"(v)); return r;
}

// ---------------------------------------------------------------------------
// Kernel A: 1x1-conv projections (R8 version — proven).
// grid = (64, 4). Full X tile resident; W double-buffered 16-k chunks.
// ---------------------------------------------------------------------------
__global__ __launch_bounds__(256) void gemm_kernel(
        const float* __restrict__ ft, const float* __restrict__ fk,
        const float* __restrict__ Wm)
{
    extern __shared__ float sm[];
    float* Xs = sm;                 // [128][64]
    float* Ws = sm + 128 * 64;      // [2][GK][128]

    const int t  = threadIdx.x;
    const int p0 = blockIdx.x * 64;
    const int n  = blockIdx.y & 1;
    const int which = blockIdx.y >> 1;
    const float* X = (which ? fk : ft) + n * C * HW;
    float*       Y = (which ? g_query : g_key) + n * C * HW;

    const int px  = (t & 15) * 4;
    const int co8 = (t >> 4) * 8;

    {
        const int cc = t >> 4;
        const int xp = (t & 15) * 4;
        #pragma unroll
        for (int it = 0; it < 8; it++) {
            int c = cc + it * 16;
            *(float4*)&Xs[c * 64 + xp] = *(const float4*)&X[c * HW + p0 + xp];
        }
    }
    const int so  = t >> 1;
    const int sk4 = (t & 1) * 8;
    auto stageW = [&](int buf, int kb) {
        float* Wb = Ws + buf * (GK * 128);
        #pragma unroll
        for (int j = 0; j < 2; j++) {
            int k4 = sk4 + j * 4;
            float4 wv = *(const float4*)&Wm[so * C + kb + k4];
            Wb[(k4 + 0) * 128 + so] = wv.x;
            Wb[(k4 + 1) * 128 + so] = wv.y;
            Wb[(k4 + 2) * 128 + so] = wv.z;
            Wb[(k4 + 3) * 128 + so] = wv.w;
        }
    };
    stageW(0, 0);

    u64 acc[4][4] = {};
    __syncthreads();

    int buf = 0;
    for (int kb = 0; kb < 8; kb++) {
        if (kb < 7) stageW(buf ^ 1, (kb + 1) * GK);
        const float* Wb = Ws + buf * (GK * 128);
        const float* Xb = Xs + (kb * GK) * 64;
        #pragma unroll
        for (int kk = 0; kk < GK; kk++) {
            float4 a0 = *(const float4*)&Wb[kk * 128 + co8];
            float4 a1 = *(const float4*)&Wb[kk * 128 + co8 + 4];
            float4 b  = *(const float4*)&Xb[kk * 64 + px];
            u64 ap0 = pk(a0.x, a0.y), ap1 = pk(a0.z, a0.w);
            u64 ap2 = pk(a1.x, a1.y), ap3 = pk(a1.z, a1.w);
            u64 b0 = pk(b.x, b.x), b1 = pk(b.y, b.y);
            u64 b2 = pk(b.z, b.z), b3 = pk(b.w, b.w);
            fma2(acc[0][0], ap0, b0); fma2(acc[0][1], ap0, b1);
            fma2(acc[0][2], ap0, b2); fma2(acc[0][3], ap0, b3);
            fma2(acc[1][0], ap1, b0); fma2(acc[1][1], ap1, b1);
            fma2(acc[1][2], ap1, b2); fma2(acc[1][3], ap1, b3);
            fma2(acc[2][0], ap2, b0); fma2(acc[2][1], ap2, b1);
            fma2(acc[2][2], ap2, b2); fma2(acc[2][3], ap2, b3);
            fma2(acc[3][0], ap3, b0); fma2(acc[3][1], ap3, b1);
            fma2(acc[3][2], ap3, b2); fma2(acc[3][3], ap3, b3);
        }
        __syncthreads();
        buf ^= 1;
    }

    #pragma unroll
    for (int j2 = 0; j2 < 4; j2++) {
        float2 v0 = upk(acc[j2][0]), v1 = upk(acc[j2][1]);
        float2 v2 = upk(acc[j2][2]), v3 = upk(acc[j2][3]);
        *(float4*)&Y[(co8 + 2 * j2)     * HW + p0 + px] =
            make_float4(v0.x, v1.x, v2.x, v3.x);
        *(float4*)&Y[(co8 + 2 * j2 + 1) * HW + p0 + px] =
            make_float4(v0.y, v1.y, v2.y, v3.y);
    }
}

// ---------------------------------------------------------------------------
// Fused kernel: sim + softmax + weighting, one block per 2x16 px tile.
// Phase B: proven R10/R11 structure: sim via smem halo tiles, 4-way
//   channel-split partials merged into 2 arrays, softmax folded over the sum.
//   Softmaxed weights are written TRANSPOSED to smem wd[81][36] — no gmem.
// Phase D: loop 4x 32-channel chunks of raw ft; halo restaged into ks;
//   256 threads own (1 ch x 4 px); w float4 broadcast-shared across ch lanes.
// ---------------------------------------------------------------------------
__global__ __launch_bounds__(288) void fused_kernel(
        const float* __restrict__ ft, float* __restrict__ out)
{
    extern __shared__ float sm[];
    float* ks   = sm;                      // CCB*BHY*BKST = 8960 floats
    float* qs   = ks + CCB * BHY * BKST;   // CCB*BTP      = 1024
    float* simp = qs + CCB * BTP;          // 2*SIMN       = 5184
    float* wd   = simp + 2 * SIMN;         // KK*WDS       = 2916

    const int t   = threadIdx.x;
    const int bx  = blockIdx.x;
    const int n   = bx >> 7;
    const int rem = bx & 127;
    const int ty0 = (rem >> 2) * BTH;
    const int tx0 = (rem & 3) * BTW;

    const float* keyg = g_key   + n * C * HW;
    const float* qg   = g_query + n * C * HW;
    const float* ftn  = ft      + n * C * HW;

    // fixed staging coordinates (computed once; shared by key and ft halos)
    const int shy = t / 24;                // halo row   (valid if t < 240)
    const int shx = t - shy * 24;          // halo col
    const int sgy = ty0 + shy - PADR;
    const int sgx = tx0 + shx - PADR;
    const bool sval = (t < 240) && ((unsigned)sgy < H) && ((unsigned)sgx < WID);
    const int sgo = sgy * WID + sgx;       // gmem offset (garbage if !sval)
    const int sso = shy * BKST + shx;      // smem offset
    const int qpx = t & 31;                // q px (valid if t < 256)
    const int qc0 = (t >> 5) & 7;          // q start channel
    const int qpy = (ty0 + (qpx >> 4)) * WID + tx0 + (qpx & 15);

    const int cq  = t / 72;
    const int r   = t - cq * 72;
    const int di  = r >> 3;
    const int pxg = r & 7;
    const int ly  = pxg >> 2;
    const int lxg = (pxg & 3) * 4;

    u64 accp[9][2] = {};

    // ===================== Phase B: sim =====================
    for (int cc = 0; cc < C; cc += CCB) {
        if (t < 240) {
            const float* src = keyg + cc * HW + sgo;
            float* dst = ks + sso;
            #pragma unroll 8
            for (int c = 0; c < CCB; c++)
                dst[c * (BHY * BKST)] = sval ? src[c * HW] : 0.f;
        }
        if (t < 256) {
            const float* src = qg + cc * HW + qpy;
            #pragma unroll
            for (int c = qc0; c < CCB; c += 8)
                qs[c * BTP + qpx] = src[c * HW];
        }
        __syncthreads();

        const int cbeg = cq * 8;
        #pragma unroll 2
        for (int c = cbeg; c < cbeg + 8; c++) {
            float4 q4 = *(const float4*)&qs[c * BTP + ly * BTW + lxg];
            const float* kp = &ks[c * (BHY * BKST) + (ly + di) * BKST + lxg];
            float4 k0 = *(const float4*)kp;
            float4 k1 = *(const float4*)(kp + 4);
            float4 k2 = *(const float4*)(kp + 8);
            const float kr[12] = {k0.x, k0.y, k0.z, k0.w,
                                  k1.x, k1.y, k1.z, k1.w,
                                  k2.x, k2.y, k2.z, k2.w};
            u64 q01 = pk(q4.x, q4.y), q23 = pk(q4.z, q4.w);
            u64 win[11];
            #pragma unroll
            for (int m = 0; m < 11; m++) win[m] = pk(kr[m], kr[m + 1]);
            #pragma unroll
            for (int dj = 0; dj < 9; dj++) {
                fma2(accp[dj][0], q01, win[dj]);
                fma2(accp[dj][1], q23, win[dj + 2]);
            }
        }
        __syncthreads();
    }

    // merge 4 partials into 2 arrays (cq0,1 -> sp0; cq2,3 -> sp1)
    const int pxb = ly * BTW + lxg;
    float* sp = simp + (cq >> 1) * SIMN;
    if ((cq & 1) == 0) {
        #pragma unroll
        for (int dj = 0; dj < 9; dj++) {
            float2 v0 = upk(accp[dj][0]), v1 = upk(accp[dj][1]);
            sp[(pxb + 0) * KK + di * 9 + dj] = v0.x;
            sp[(pxb + 1) * KK + di * 9 + dj] = v0.y;
            sp[(pxb + 2) * KK + di * 9 + dj] = v1.x;
            sp[(pxb + 3) * KK + di * 9 + dj] = v1.y;
        }
    }
    __syncthreads();
    if (cq & 1) {
        #pragma unroll
        for (int dj = 0; dj < 9; dj++) {
            float2 v0 = upk(accp[dj][0]), v1 = upk(accp[dj][1]);
            sp[(pxb + 0) * KK + di * 9 + dj] += v0.x;
            sp[(pxb + 1) * KK + di * 9 + dj] += v0.y;
            sp[(pxb + 2) * KK + di * 9 + dj] += v1.x;
            sp[(pxb + 3) * KK + di * 9 + dj] += v1.y;
        }
    }
    __syncthreads();

    // ============ softmax over 81 taps -> transposed wd[81][36] ============
    if (t < 256) {
        const int px = t >> 3;
        const int q  = t & 7;
        float* r0 = &simp[px * KK];
        float* r1 = r0 + SIMN;
        float m = -1e30f;
        for (int k = q; k < KK; k += 8) {
            float v = r0[k] + r1[k];
            r0[k] = v;
            m = fmaxf(m, v);
        }
        m = fmaxf(m, __shfl_xor_sync(0xffffffffu, m, 1));
        m = fmaxf(m, __shfl_xor_sync(0xffffffffu, m, 2));
        m = fmaxf(m, __shfl_xor_sync(0xffffffffu, m, 4));
        float s = 0.f;
        for (int k = q; k < KK; k += 8) {
            float e = __expf(r0[k] - m);
            r0[k] = e;
            s += e;
        }
        s += __shfl_xor_sync(0xffffffffu, s, 1);
        s += __shfl_xor_sync(0xffffffffu, s, 2);
        s += __shfl_xor_sync(0xffffffffu, s, 4);
        const float inv = 1.f / s;
        for (int k = q; k < KK; k += 8)
            wd[k * WDS + px] = r0[k] * inv;
    }
    __syncthreads();

    // ===================== Phase D: weighting =====================
    const int dch = t >> 3;                // channel within chunk (t < 256)
    float* on = out + n * C * HW;
    const int opix = (ty0 + ly) * WID + tx0 + lxg;

    for (int cc = 0; cc < C; cc += CCB) {
        // restage ft halo into ks (same fixed coords)
        if (t < 240) {
            const float* src = ftn + cc * HW + sgo;
            float* dst = ks + sso;
            #pragma unroll 8
            for (int c = 0; c < CCB; c++)
                dst[c * (BHY * BKST)] = sval ? src[c * HW] : 0.f;
        }
        __syncthreads();

        if (t < 256) {
            u64 a0 = 0, a1 = 0;
            #pragma unroll
            for (int ddi = 0; ddi < 9; ddi++) {
                const float* f = &ks[dch * (BHY * BKST) + (ly + ddi) * BKST + lxg];
                float4 x0 = *(const float4*)f;
                float4 x1 = *(const float4*)(f + 4);
                float4 x2 = *(const float4*)(f + 8);
                const float fr[12] = {x0.x, x0.y, x0.z, x0.w,
                                      x1.x, x1.y, x1.z, x1.w,
                                      x2.x, x2.y, x2.z, x2.w};
                u64 win[11];
                #pragma unroll
                for (int m = 0; m < 11; m++) win[m] = pk(fr[m], fr[m + 1]);
                #pragma unroll
                for (int dj = 0; dj < 9; dj++) {
                    float4 w4 = *(const float4*)&wd[(ddi * 9 + dj) * WDS + ly * BTW + lxg];
                    fma2(a0, pk(w4.x, w4.y), win[dj]);
                    fma2(a1, pk(w4.z, w4.w), win[dj + 2]);
                }
            }
            float2 v0 = upk(a0), v1 = upk(a1);
            *(float4*)&on[(cc + dch) * HW + opix] =
                make_float4(v0.x, v0.y, v1.x, v1.y);
        }
        __syncthreads();
    }
}

// ---------------------------------------------------------------------------
extern "C" void kernel_launch(void* const* d_in, const int* in_sizes, int n_in,
                              void* d_out, int out_size)
{
    const float* ft = (const float*)d_in[0];
    const float* fk = (const float*)d_in[1];
    const float* Wm = (const float*)d_in[2];
    float* out = (float*)d_out;

    const int smA = (128 * 64 + 2 * GK * 128) * (int)sizeof(float);   // 49152
    const int smF = (CCB * BHY * BKST + CCB * BTP + 2 * SIMN + KK * WDS)
                    * (int)sizeof(float);                              // 72336
    cudaFuncSetAttribute(gemm_kernel,
                         cudaFuncAttributeMaxDynamicSharedMemorySize, smA);
    cudaFuncSetAttribute(fused_kernel,
                         cudaFuncAttributeMaxDynamicSharedMemorySize, smF);

    gemm_kernel<<<dim3(HW / 64, 4), 256, smA>>>(ft, fk, Wm);
    fused_kernel<<<NB * (H / BTH) * (WID / BTW), 288, smF>>>(ft, out);
}

// round 15
// speedup vs baseline: 1.6271x; 1.1400x over previous
#include <cuda_runtime.h>

// Problem constants
#define NB   2
#define C    128
#define H    64
#define WID  64
#define HW   4096       // H*W
#define KK   81         // L*L
#define PADR 4          // L/2

// fused kernel tiling (2x16 px tiles -> 256 blocks, 288 threads)
#define BTH  2
#define BTW  16
#define BTP  32         // px per tile
#define BHY  10         // 2 + 8 halo rows
#define BHX  24
#define BKST 28         // padded halo row stride
#define CCB  32         // B channel chunk
#define CSTR (BHY*BKST) // 280: channel stride in halo buffer
#define SIMN 2592       // BTP*KK
#define WDS  36         // wd row stride

// fused smem layout (float offsets)
#define OF_WD   0
#define OF_KS   2916                  // B: 2 x 8960 bufs; D: 64ch x 280
#define KSBUF   8960                  // CCB*CSTR
#define OF_QS   20836                 // 2 x 1024
#define QSBUF   1024
#define OF_SIMP 22884                 // 2 x SIMN
#define SMF     28068                 // total floats (109.6 KB)

#define GK   16         // gemm W k-chunk

// Scratch (allocation-free rule: __device__ globals)
__device__ float g_key   [NB * C * HW];
__device__ float g_query [NB * C * HW];

// ---- packed fp32x2 helpers ----
typedef unsigned long long u64;
__device__ __forceinline__ u64 pk(float lo, float hi) {
    u64 r; asm("mov.b64 %0, {%1, %2};" : "=l"(r) : "f"(lo), "f"(hi)); return r;
}
__device__ __forceinline__ void fma2(u64& d, u64 a, u64 b) {
    asm("fma.rn.f32x2 %0, %1, %2, %0;" : "+l"(d) : "l"(a), "l"(b));
}
__device__ __forceinline__ float2 upk(u64 v) {
    float2 r; asm("mov.b64 {%0, %1}, %2;" : "=f"(r.x), "=f"(r.y) : "l"(v)); return r;
}

// ---- cp.async helpers ----
__device__ __forceinline__ void cpa4(unsigned saddr, const void* g) {
    asm volatile("cp.async.ca.shared.global [%0], [%1], 4;" :: "r"(saddr), "l"(g));
}
#define CP_COMMIT() asm volatile("cp.async.commit_group;" ::: "memory")
#define CP_WAIT0()  asm volatile("cp.async.wait_group 0;" ::: "memory")

// ---------------------------------------------------------------------------
// Kernel A: 1x1-conv projections (R8 version — proven).
// ---------------------------------------------------------------------------
__global__ __launch_bounds__(256) void gemm_kernel(
        const float* __restrict__ ft, const float* __restrict__ fk,
        const float* __restrict__ Wm)
{
    extern __shared__ float sm[];
    float* Xs = sm;                 // [128][64]
    float* Ws = sm + 128 * 64;      // [2][GK][128]

    const int t  = threadIdx.x;
    const int p0 = blockIdx.x * 64;
    const int n  = blockIdx.y & 1;
    const int which = blockIdx.y >> 1;
    const float* X = (which ? fk : ft) + n * C * HW;
    float*       Y = (which ? g_query : g_key) + n * C * HW;

    const int px  = (t & 15) * 4;
    const int co8 = (t >> 4) * 8;

    {
        const int cc = t >> 4;
        const int xp = (t & 15) * 4;
        #pragma unroll
        for (int it = 0; it < 8; it++) {
            int c = cc + it * 16;
            *(float4*)&Xs[c * 64 + xp] = *(const float4*)&X[c * HW + p0 + xp];
        }
    }
    const int so  = t >> 1;
    const int sk4 = (t & 1) * 8;
    auto stageW = [&](int buf, int kb) {
        float* Wb = Ws + buf * (GK * 128);
        #pragma unroll
        for (int j = 0; j < 2; j++) {
            int k4 = sk4 + j * 4;
            float4 wv = *(const float4*)&Wm[so * C + kb + k4];
            Wb[(k4 + 0) * 128 + so] = wv.x;
            Wb[(k4 + 1) * 128 + so] = wv.y;
            Wb[(k4 + 2) * 128 + so] = wv.z;
            Wb[(k4 + 3) * 128 + so] = wv.w;
        }
    };
    stageW(0, 0);

    u64 acc[4][4] = {};
    __syncthreads();

    int buf = 0;
    for (int kb = 0; kb < 8; kb++) {
        if (kb < 7) stageW(buf ^ 1, (kb + 1) * GK);
        const float* Wb = Ws + buf * (GK * 128);
        const float* Xb = Xs + (kb * GK) * 64;
        #pragma unroll
        for (int kk = 0; kk < GK; kk++) {
            float4 a0 = *(const float4*)&Wb[kk * 128 + co8];
            float4 a1 = *(const float4*)&Wb[kk * 128 + co8 + 4];
            float4 b  = *(const float4*)&Xb[kk * 64 + px];
            u64 ap0 = pk(a0.x, a0.y), ap1 = pk(a0.z, a0.w);
            u64 ap2 = pk(a1.x, a1.y), ap3 = pk(a1.z, a1.w);
            u64 b0 = pk(b.x, b.x), b1 = pk(b.y, b.y);
            u64 b2 = pk(b.z, b.z), b3 = pk(b.w, b.w);
            fma2(acc[0][0], ap0, b0); fma2(acc[0][1], ap0, b1);
            fma2(acc[0][2], ap0, b2); fma2(acc[0][3], ap0, b3);
            fma2(acc[1][0], ap1, b0); fma2(acc[1][1], ap1, b1);
            fma2(acc[1][2], ap1, b2); fma2(acc[1][3], ap1, b3);
            fma2(acc[2][0], ap2, b0); fma2(acc[2][1], ap2, b1);
            fma2(acc[2][2], ap2, b2); fma2(acc[2][3], ap2, b3);
            fma2(acc[3][0], ap3, b0); fma2(acc[3][1], ap3, b1);
            fma2(acc[3][2], ap3, b2); fma2(acc[3][3], ap3, b3);
        }
        __syncthreads();
        buf ^= 1;
    }

    #pragma unroll
    for (int j2 = 0; j2 < 4; j2++) {
        float2 v0 = upk(acc[j2][0]), v1 = upk(acc[j2][1]);
        float2 v2 = upk(acc[j2][2]), v3 = upk(acc[j2][3]);
        *(float4*)&Y[(co8 + 2 * j2)     * HW + p0 + px] =
            make_float4(v0.x, v1.x, v2.x, v3.x);
        *(float4*)&Y[(co8 + 2 * j2 + 1) * HW + p0 + px] =
            make_float4(v0.y, v1.y, v2.y, v3.y);
    }
}

// ---------------------------------------------------------------------------
// Fused kernel v2: sim + softmax + weighting.
// Phase B: cp.async software pipeline, double-buffered ks/qs (1 sync/chunk).
// Phase D: 2 chunks of 64 channels, 2 ch/thread sharing w4 loads; chunk-0
//   staging overlapped with merge+softmax.
// ---------------------------------------------------------------------------
__global__ void __launch_bounds__(288, 2) fused_kernel(
        const float* __restrict__ ft, float* __restrict__ out)
{
    extern __shared__ float sm[];
    float* wd     = sm + OF_WD;     // [81][36]
    float* ksbase = sm + OF_KS;
    float* qsbase = sm + OF_QS;
    float* simp   = sm + OF_SIMP;   // [2][SIMN]

    const int t   = threadIdx.x;
    const int bx  = blockIdx.x;
    const int n   = bx >> 7;
    const int rem = bx & 127;
    const int ty0 = (rem >> 2) * BTH;
    const int tx0 = (rem & 3) * BTW;

    const float* keyg = g_key   + n * C * HW;
    const float* qg   = g_query + n * C * HW;
    const float* ftn  = ft      + n * C * HW;

    // fixed staging coordinates
    const int shy = t / 24;
    const int shx = t - shy * 24;
    const int sgy = ty0 + shy - PADR;
    const int sgx = tx0 + shx - PADR;
    const bool sval = (t < 240) && ((unsigned)sgy < H) && ((unsigned)sgx < WID);
    const int sgo = sgy * WID + sgx;
    const int sso = shy * BKST + shx;
    const int qpx = t & 31;
    const int qc0 = (t >> 5) & 7;
    const int qpy = (ty0 + (qpx >> 4)) * WID + tx0 + (qpx & 15);

    const unsigned ks_sh = (unsigned)__cvta_generic_to_shared(ksbase) + sso * 4;
    const unsigned qs_sh = (unsigned)__cvta_generic_to_shared(qsbase) + qpx * 4;

    const int cq  = t / 72;
    const int r   = t - cq * 72;
    const int di  = r >> 3;
    const int pxg = r & 7;
    const int ly  = pxg >> 2;
    const int lxg = (pxg & 3) * 4;

    // --- staging issuers ---
    auto stageB = [&](int buf, int cc) {
        if (t < 240) {
            if (sval) {
                const float* src = keyg + cc * HW + sgo;
                unsigned d = ks_sh + buf * (KSBUF * 4);
                #pragma unroll 8
                for (int c = 0; c < CCB; c++)
                    cpa4(d + c * (CSTR * 4), src + c * HW);
            } else {
                float* d = ksbase + buf * KSBUF + sso;
                #pragma unroll 8
                for (int c = 0; c < CCB; c++)
                    d[c * CSTR] = 0.f;
            }
        }
        if (t < 256) {
            const float* srcq = qg + cc * HW + qpy;
            unsigned d = qs_sh + buf * (QSBUF * 4);
            #pragma unroll
            for (int j = 0; j < 4; j++)
                cpa4(d + (qc0 + 8 * j) * (BTP * 4), srcq + (qc0 + 8 * j) * HW);
        }
        CP_COMMIT();
    };
    auto stageD = [&](int cc) {      // 64 channels into ks region
        if (t < 240) {
            if (sval) {
                const float* src = ftn + cc * HW + sgo;
                #pragma unroll 8
                for (int c = 0; c < 64; c++)
                    cpa4(ks_sh + c * (CSTR * 4), src + c * HW);
            } else {
                float* d = ksbase + sso;
                #pragma unroll 8
                for (int c = 0; c < 64; c++)
                    d[c * CSTR] = 0.f;
            }
        }
        CP_COMMIT();
    };

    u64 accp[9][2] = {};

    // ===================== Phase B: sim (pipelined) =====================
    stageB(0, 0);
    CP_WAIT0();
    __syncthreads();
    for (int i = 0; i < 4; i++) {
        if (i < 3) stageB((i + 1) & 1, (i + 1) * CCB);
        const float* ks = ksbase + (i & 1) * KSBUF;
        const float* qs = qsbase + (i & 1) * QSBUF;
        const int cbeg = cq * 8;
        #pragma unroll 2
        for (int c = cbeg; c < cbeg + 8; c++) {
            float4 q4 = *(const float4*)&qs[c * BTP + ly * BTW + lxg];
            const float* kp = &ks[c * CSTR + (ly + di) * BKST + lxg];
            float4 k0 = *(const float4*)kp;
            float4 k1 = *(const float4*)(kp + 4);
            float4 k2 = *(const float4*)(kp + 8);
            const float kr[12] = {k0.x, k0.y, k0.z, k0.w,
                                  k1.x, k1.y, k1.z, k1.w,
                                  k2.x, k2.y, k2.z, k2.w};
            u64 q01 = pk(q4.x, q4.y), q23 = pk(q4.z, q4.w);
            u64 win[11];
            #pragma unroll
            for (int m = 0; m < 11; m++) win[m] = pk(kr[m], kr[m + 1]);
            #pragma unroll
            for (int dj = 0; dj < 9; dj++) {
                fma2(accp[dj][0], q01, win[dj]);
                fma2(accp[dj][1], q23, win[dj + 2]);
            }
        }
        CP_WAIT0();
        __syncthreads();
    }

    // issue D chunk-0 staging now — overlaps merge + softmax
    stageD(0);

    // merge 4 partials into 2 arrays (cq0,1 -> sp0; cq2,3 -> sp1)
    const int pxb = ly * BTW + lxg;
    float* sp = simp + (cq >> 1) * SIMN;
    if ((cq & 1) == 0) {
        #pragma unroll
        for (int dj = 0; dj < 9; dj++) {
            float2 v0 = upk(accp[dj][0]), v1 = upk(accp[dj][1]);
            sp[(pxb + 0) * KK + di * 9 + dj] = v0.x;
            sp[(pxb + 1) * KK + di * 9 + dj] = v0.y;
            sp[(pxb + 2) * KK + di * 9 + dj] = v1.x;
            sp[(pxb + 3) * KK + di * 9 + dj] = v1.y;
        }
    }
    __syncthreads();
    if (cq & 1) {
        #pragma unroll
        for (int dj = 0; dj < 9; dj++) {
            float2 v0 = upk(accp[dj][0]), v1 = upk(accp[dj][1]);
            sp[(pxb + 0) * KK + di * 9 + dj] += v0.x;
            sp[(pxb + 1) * KK + di * 9 + dj] += v0.y;
            sp[(pxb + 2) * KK + di * 9 + dj] += v1.x;
            sp[(pxb + 3) * KK + di * 9 + dj] += v1.y;
        }
    }
    __syncthreads();

    // softmax over 81 taps -> transposed wd[81][36]
    if (t < 256) {
        const int px = t >> 3;
        const int q  = t & 7;
        float* r0 = &simp[px * KK];
        float* r1 = r0 + SIMN;
        float m = -1e30f;
        for (int k = q; k < KK; k += 8) {
            float v = r0[k] + r1[k];
            r0[k] = v;
            m = fmaxf(m, v);
        }
        m = fmaxf(m, __shfl_xor_sync(0xffffffffu, m, 1));
        m = fmaxf(m, __shfl_xor_sync(0xffffffffu, m, 2));
        m = fmaxf(m, __shfl_xor_sync(0xffffffffu, m, 4));
        float s = 0.f;
        for (int k = q; k < KK; k += 8) {
            float e = __expf(r0[k] - m);
            r0[k] = e;
            s += e;
        }
        s += __shfl_xor_sync(0xffffffffu, s, 1);
        s += __shfl_xor_sync(0xffffffffu, s, 2);
        s += __shfl_xor_sync(0xffffffffu, s, 4);
        const float inv = 1.f / s;
        for (int k = q; k < KK; k += 8)
            wd[k * WDS + px] = r0[k] * inv;
    }
    CP_WAIT0();
    __syncthreads();

    // ===================== Phase D: weighting =====================
    const int chp = t >> 3;             // 0..31 channel-pair (t < 256)
    float* on = out + n * C * HW;
    const int opix = (ty0 + ly) * WID + tx0 + lxg;

    #pragma unroll
    for (int cc2 = 0; cc2 < 2; cc2++) {
        const int cc = cc2 * 64;
        if (t < 256) {
            u64 a00 = 0, a01 = 0, a10 = 0, a11 = 0;
            #pragma unroll
            for (int ddi = 0; ddi < 9; ddi++) {
                const float* f0 = &ksbase[chp * CSTR + (ly + ddi) * BKST + lxg];
                const float* f1 = f0 + 32 * CSTR;
                float4 x0 = *(const float4*)f0;
                float4 x1 = *(const float4*)(f0 + 4);
                float4 x2 = *(const float4*)(f0 + 8);
                float4 y0 = *(const float4*)f1;
                float4 y1 = *(const float4*)(f1 + 4);
                float4 y2 = *(const float4*)(f1 + 8);
                const float fr0[12] = {x0.x, x0.y, x0.z, x0.w, x1.x, x1.y, x1.z, x1.w,
                                       x2.x, x2.y, x2.z, x2.w};
                const float fr1[12] = {y0.x, y0.y, y0.z, y0.w, y1.x, y1.y, y1.z, y1.w,
                                       y2.x, y2.y, y2.z, y2.w};
                u64 w0[11], w1[11];
                #pragma unroll
                for (int m = 0; m < 11; m++) {
                    w0[m] = pk(fr0[m], fr0[m + 1]);
                    w1[m] = pk(fr1[m], fr1[m + 1]);
                }
                #pragma unroll
                for (int dj = 0; dj < 9; dj++) {
                    float4 w4 = *(const float4*)&wd[(ddi * 9 + dj) * WDS + ly * BTW + lxg];
                    u64 wa = pk(w4.x, w4.y), wb = pk(w4.z, w4.w);
                    fma2(a00, wa, w0[dj]);
                    fma2(a01, wb, w0[dj + 2]);
                    fma2(a10, wa, w1[dj]);
                    fma2(a11, wb, w1[dj + 2]);
                }
            }
            {
                float2 v0 = upk(a00), v1 = upk(a01);
                *(float4*)&on[(cc + chp) * HW + opix] =
                    make_float4(v0.x, v0.y, v1.x, v1.y);
            }
            {
                float2 v0 = upk(a10), v1 = upk(a11);
                *(float4*)&on[(cc + chp + 32) * HW + opix] =
                    make_float4(v0.x, v0.y, v1.x, v1.y);
            }
        }
        if (cc2 == 0) {
            __syncthreads();            // all reads of chunk-0 halo done
            stageD(64);
            CP_WAIT0();
            __syncthreads();
        }
    }
}

// ---------------------------------------------------------------------------
extern "C" void kernel_launch(void* const* d_in, const int* in_sizes, int n_in,
                              void* d_out, int out_size)
{
    const float* ft = (const float*)d_in[0];
    const float* fk = (const float*)d_in[1];
    const float* Wm = (const float*)d_in[2];
    float* out = (float*)d_out;

    const int smA = (128 * 64 + 2 * GK * 128) * (int)sizeof(float);   // 49152
    const int smF = SMF * (int)sizeof(float);                          // 112272
    cudaFuncSetAttribute(gemm_kernel,
                         cudaFuncAttributeMaxDynamicSharedMemorySize, smA);
    cudaFuncSetAttribute(fused_kernel,
                         cudaFuncAttributeMaxDynamicSharedMemorySize, smF);

    gemm_kernel<<<dim3(HW / 64, 4), 256, smA>>>(ft, fk, Wm);
    fused_kernel<<<NB * (H / BTH) * (WID / BTW), 288, smF>>>(ft, out);
}